// round 13
// baseline (speedup 1.0000x reference)
#include <cuda_runtime.h>
#include <cuda_bf16.h>

#define N_NODES 100000
#define N_EDGES 3200000
#define N_GRAPHS 256
// DIMS: 38 -> 64 -> 32 -> 16

// ---------------- scratch (static device globals; no allocs) ----------------
__device__ float g_x40 [N_NODES * 40];
__device__ float g_agg0[N_NODES * 40];
__device__ float g_agg1[N_NODES * 32];
__device__ float g_agg2[N_NODES * 16];
__device__ float g_y1[N_NODES * 32];   // h1 @ Wrel1^T   (scatter1 payload)
__device__ float g_z1[N_NODES * 32];   // h1 @ Wroot1^T  (node1 self term)
__device__ float g_y2[N_NODES * 16];   // h2 @ Wrel2^T   (scatter2 payload)
__device__ float g_z2[N_NODES * 16];   // h2 @ Wroot2^T  (node2 self term)
__device__ int   g_src[N_EDGES];
__device__ int   g_dst[N_EDGES];
__device__ float g_pool[N_GRAPHS * 16];
__device__ float g_cnt[N_GRAPHS];
__device__ int   g_ei_is64;
__device__ int   g_b_is64;

__device__ __forceinline__ void red_add_v4(float* addr, float4 v) {
    asm volatile("red.global.add.v4.f32 [%0], {%1,%2,%3,%4};"
                 :: "l"(addr), "f"(v.x), "f"(v.y), "f"(v.z), "f"(v.w)
                 : "memory");
}

// ---------------- dtype detection (int32 vs int64 buffers) ------------------
__global__ void k_detect(const int* __restrict__ ei_raw,
                         const int* __restrict__ b_raw) {
    int nz = 0;
    #pragma unroll
    for (int i = 0; i < 64; i++) nz |= ei_raw[2 * i + 1];
    g_ei_is64 = (nz == 0) ? 1 : 0;
    g_b_is64 = (b_raw[N_NODES - 1] == 0) ? 1 : 0;
}

// ---------------- fused prep: convert indices + zero + pack x ---------------
__global__ void k_prep(const float* __restrict__ x,
                       const int* __restrict__ ei_raw) {
    long long i = (long long)blockIdx.x * blockDim.x + threadIdx.x;
    long long stride = (long long)gridDim.x * blockDim.x;
    int is64 = g_ei_is64;
    for (long long e = i; e < N_EDGES; e += stride) {
        if (is64) {
            g_src[e] = ei_raw[2 * e];
            g_dst[e] = ei_raw[2 * ((long long)N_EDGES + e)];
        } else {
            g_src[e] = ei_raw[e];
            g_dst[e] = ei_raw[N_EDGES + e];
        }
    }
    for (long long k = i; k < (long long)N_NODES * 40; k += stride) {
        g_agg0[k] = 0.f;
        int j = (int)(k % 40);
        g_x40[k] = (j < 38) ? x[(k / 40) * 38 + j] : 0.f;
    }
    for (long long k = i; k < (long long)N_NODES * 32; k += stride) g_agg1[k] = 0.f;
    for (long long k = i; k < (long long)N_NODES * 16; k += stride) g_agg2[k] = 0.f;
    for (long long k = i; k < N_GRAPHS * 16; k += stride) g_pool[k] = 0.f;
    for (long long k = i; k < N_GRAPHS; k += stride) g_cnt[k] = 0.f;
}

// ---------------- scatters (proven at REDG/L2-byte floor) -------------------
__global__ void k_scatter0() {
    long long idx = (long long)blockIdx.x * blockDim.x + threadIdx.x;
    if (idx >= (long long)N_EDGES * 10) return;
    int e = (int)(idx / 10);
    int c = (int)(idx - (long long)e * 10);
    int s = g_src[e];
    int d = g_dst[e];
    float4 v = *(const float4*)&g_x40[s * 40 + c * 4];
    red_add_v4(&g_agg0[d * 40 + c * 4], v);
}

__global__ void k_scatter1() {
    long long idx = (long long)blockIdx.x * blockDim.x + threadIdx.x;
    if (idx >= (long long)N_EDGES * 8) return;
    int e = (int)(idx >> 3);
    int c = (int)(idx & 7);
    int s = g_src[e];
    int d = g_dst[e];
    float4 v = *(const float4*)&g_y1[s * 32 + c * 4];
    red_add_v4(&g_agg1[d * 32 + c * 4], v);
}

__global__ void k_scatter2() {
    long long idx = (long long)blockIdx.x * blockDim.x + threadIdx.x;
    if (idx >= (long long)N_EDGES * 4) return;
    int e = (int)(idx >> 2);
    int c = (int)(idx & 3);
    int s = g_src[e];
    int d = g_dst[e];
    float4 v = *(const float4*)&g_y2[s * 16 + c * 4];
    red_add_v4(&g_agg2[d * 16 + c * 4], v);
}

// ---------------- node kernel 0: h1 (regs) -> y1 AND z1 (fused) -------------
// thread: o = t&63 (output), sl = t>>6 (4 slots); node nl = sl + 4q, q<4.
// Phase 2 computes BOTH y1 = h1@Wrel1^T and z1 = h1@Wroot1^T from shared h.
__global__ void __launch_bounds__(256, 2)
k_node0(const float* __restrict__ Wr0,  // [64,38]
        const float* __restrict__ b0,   // [64]
        const float* __restrict__ Wt0,  // [64,38]
        const float* __restrict__ Wr1,  // [32,64]
        const float* __restrict__ Wt1)  // [32,64]
{
    int t = threadIdx.x;
    int o = t & 63, sl = t >> 6;
    float wr[40], wt[40];
    #pragma unroll
    for (int j = 0; j < 40; j++) {
        wr[j] = (j < 38) ? Wr0[o * 38 + j] : 0.f;
        wt[j] = (j < 38) ? Wt0[o * 38 + j] : 0.f;
    }
    float bias = b0[o];
    int oo = o & 31, jb = (o < 32) ? 0 : 32;

    __shared__ float  sW1y[32 * 65];         // Wrel1 [32x64] row stride 65
    __shared__ float  sW1z[32 * 65];         // Wroot1 [32x64] row stride 65
    __shared__ float4 sa4[16][10], sx4[16][10];
    __shared__ float  sh[16][64];
    __shared__ float  spy[16][64], spz[16][64];
    for (int i = t; i < 32 * 64; i += 256) {
        sW1y[(i >> 6) * 65 + (i & 63)] = Wr1[i];
        sW1z[(i >> 6) * 65 + (i & 63)] = Wt1[i];
    }
    __syncthreads();

    for (int nbase = blockIdx.x * 16; nbase < N_NODES; nbase += gridDim.x * 16) {
        for (int i = t; i < 320; i += 256) {
            int n2 = i / 20, r = i % 20;
            int nn = nbase + n2;
            if (nn < N_NODES) {
                if (r < 10) sa4[n2][r] = *(const float4*)&g_agg0[nn * 40 + r * 4];
                else        sx4[n2][r - 10] = *(const float4*)&g_x40[nn * 40 + (r - 10) * 4];
            }
        }
        __syncthreads();
        float h0 = bias, h1v = bias, h2v = bias, h3 = bias;
        #pragma unroll
        for (int c = 0; c < 10; c++) {
            float w0 = wr[4*c+0], w1_ = wr[4*c+1], w2_ = wr[4*c+2], w3 = wr[4*c+3];
            float u0 = wt[4*c+0], u1 = wt[4*c+1], u2 = wt[4*c+2], u3 = wt[4*c+3];
            float4 a, xv;
            a = sa4[sl][c];      xv = sx4[sl][c];
            h0 += w0*a.x + w1_*a.y + w2_*a.z + w3*a.w + u0*xv.x + u1*xv.y + u2*xv.z + u3*xv.w;
            a = sa4[sl+4][c];    xv = sx4[sl+4][c];
            h1v += w0*a.x + w1_*a.y + w2_*a.z + w3*a.w + u0*xv.x + u1*xv.y + u2*xv.z + u3*xv.w;
            a = sa4[sl+8][c];    xv = sx4[sl+8][c];
            h2v += w0*a.x + w1_*a.y + w2_*a.z + w3*a.w + u0*xv.x + u1*xv.y + u2*xv.z + u3*xv.w;
            a = sa4[sl+12][c];   xv = sx4[sl+12][c];
            h3 += w0*a.x + w1_*a.y + w2_*a.z + w3*a.w + u0*xv.x + u1*xv.y + u2*xv.z + u3*xv.w;
        }
        h0 = tanhf(h0); h1v = tanhf(h1v); h2v = tanhf(h2v); h3 = tanhf(h3);
        float hq[4] = {h0, h1v, h2v, h3};
        #pragma unroll
        for (int q = 0; q < 4; q++) sh[sl + 4 * q][o] = hq[q];
        __syncthreads();
        #pragma unroll
        for (int q = 0; q < 4; q++) {
            int nl = sl + 4 * q;
            float py = 0.f, pz = 0.f;
            #pragma unroll
            for (int c = 0; c < 8; c++) {
                float4 hv = *(const float4*)&sh[nl][jb + c * 4];
                const float* wy = &sW1y[oo * 65 + jb + c * 4];
                const float* wz = &sW1z[oo * 65 + jb + c * 4];
                py += wy[0]*hv.x + wy[1]*hv.y + wy[2]*hv.z + wy[3]*hv.w;
                pz += wz[0]*hv.x + wz[1]*hv.y + wz[2]*hv.z + wz[3]*hv.w;
            }
            spy[nl][o] = py;
            spz[nl][o] = pz;
        }
        __syncthreads();
        if (o < 32) {
            #pragma unroll
            for (int q = 0; q < 4; q++) {
                int nl = sl + 4 * q, node = nbase + nl;
                if (node < N_NODES) {
                    g_y1[node * 32 + o] = spy[nl][o] + spy[nl][o + 32];
                    g_z1[node * 32 + o] = spz[nl][o] + spz[nl][o + 32];
                }
            }
        }
        __syncthreads();
    }
}

// ---------------- node kernel 1: elementwise tanh + tiny outer-product ------
// lane = node. h2 = tanh(agg1 + z1 + b1); y2 = h2@Wrel2^T; z2 = h2@Wroot2^T.
__global__ void __launch_bounds__(256, 2)
k_node1(const float* __restrict__ b1,   // [32]
        const float* __restrict__ Wr2,  // [16,32]
        const float* __restrict__ Wt2)  // [16,32]
{
    __shared__ float sWy[32 * 16], sWz[32 * 16], sb1[32];  // transposed [j][oo]
    int t = threadIdx.x;
    for (int i = t; i < 512; i += 256) {
        int j = i >> 4, oo = i & 15;
        sWy[i] = Wr2[oo * 32 + j];
        sWz[i] = Wt2[oo * 32 + j];
    }
    if (t < 32) sb1[t] = b1[t];
    __syncthreads();
    int lane = t & 31, wid = t >> 5;

    for (int nbase = blockIdx.x * 256; nbase < N_NODES; nbase += gridDim.x * 256) {
        int node = nbase + wid * 32 + lane;
        bool valid = node < N_NODES;
        int nc = valid ? node : (N_NODES - 1);
        float h2[32];
        #pragma unroll
        for (int c = 0; c < 8; c++) {
            float4 a = *(const float4*)&g_agg1[nc * 32 + c * 4];
            float4 z = *(const float4*)&g_z1 [nc * 32 + c * 4];
            h2[4*c+0] = tanhf(a.x + z.x + sb1[4*c+0]);
            h2[4*c+1] = tanhf(a.y + z.y + sb1[4*c+1]);
            h2[4*c+2] = tanhf(a.z + z.z + sb1[4*c+2]);
            h2[4*c+3] = tanhf(a.w + z.w + sb1[4*c+3]);
        }
        float ay[16], az[16];
        #pragma unroll
        for (int k = 0; k < 16; k++) { ay[k] = 0.f; az[k] = 0.f; }
        #pragma unroll
        for (int j = 0; j < 32; j++) {
            float h = h2[j];
            #pragma unroll
            for (int c = 0; c < 4; c++) {
                float4 wy = *(const float4*)&sWy[j * 16 + c * 4];  // broadcast
                float4 wz = *(const float4*)&sWz[j * 16 + c * 4];  // broadcast
                ay[4*c+0] += wy.x * h; ay[4*c+1] += wy.y * h;
                ay[4*c+2] += wy.z * h; ay[4*c+3] += wy.w * h;
                az[4*c+0] += wz.x * h; az[4*c+1] += wz.y * h;
                az[4*c+2] += wz.z * h; az[4*c+3] += wz.w * h;
            }
        }
        if (valid) {
            #pragma unroll
            for (int c = 0; c < 4; c++) {
                *(float4*)&g_y2[node * 16 + c * 4] =
                    make_float4(ay[4*c], ay[4*c+1], ay[4*c+2], ay[4*c+3]);
                *(float4*)&g_z2[node * 16 + c * 4] =
                    make_float4(az[4*c], az[4*c+1], az[4*c+2], az[4*c+3]);
            }
        }
    }
}

// ---------------- node kernel 2 + pooling: pure elementwise -----------------
__global__ void k_node2_pool(const int* __restrict__ batch_raw,
                             const float* __restrict__ b2)   // [16]
{
    int idx = blockIdx.x * blockDim.x + threadIdx.x;
    if (idx >= N_NODES * 16) return;
    int node = idx >> 4, o = idx & 15;
    float acc = g_agg2[idx] + g_z2[idx] + __ldg(&b2[o]);
    int g = g_b_is64 ? batch_raw[2 * node] : batch_raw[node];
    atomicAdd(&g_pool[g * 16 + o], acc);
    if (o == 0) atomicAdd(&g_cnt[g], 1.0f);
}

// ---------------- final: out = tanh(pool / max(cnt,1)) ----------------------
__global__ void k_final(float* __restrict__ out) {
    int t = blockIdx.x * blockDim.x + threadIdx.x;
    if (t < N_GRAPHS * 16) {
        int g = t >> 4;
        out[t] = tanhf(g_pool[t] / fmaxf(g_cnt[g], 1.0f));
    }
}

extern "C" void kernel_launch(void* const* d_in, const int* in_sizes, int n_in,
                              void* d_out, int out_size) {
    const float* x         = (const float*)d_in[0];
    const int*   ei_raw    = (const int*)d_in[1];
    const int*   batch_raw = (const int*)d_in[2];
    const float* Wr0 = (const float*)d_in[3];
    const float* b0  = (const float*)d_in[4];
    const float* Wt0 = (const float*)d_in[5];
    const float* Wr1 = (const float*)d_in[6];
    const float* b1  = (const float*)d_in[7];
    const float* Wt1 = (const float*)d_in[8];
    const float* Wr2 = (const float*)d_in[9];
    const float* b2  = (const float*)d_in[10];
    const float* Wt2 = (const float*)d_in[11];
    float* out = (float*)d_out;

    k_detect<<<1, 1>>>(ei_raw, batch_raw);
    k_prep<<<2048, 256>>>(x, ei_raw);
    // layer 0: scatter raw x; node0 emits y1 (rel) and z1 (root) directly
    k_scatter0<<<(int)(((long long)N_EDGES * 10 + 255) / 256), 256>>>();
    k_node0<<<592, 256>>>(Wr0, b0, Wt0, Wr1, Wt1);
    // layer 1: scatter y1; node1 is elementwise tanh + 32->16 outer products
    k_scatter1<<<(int)(((long long)N_EDGES * 8 + 255) / 256), 256>>>();
    k_node1<<<592, 256>>>(b1, Wr2, Wt2);
    // layer 2: scatter y2; node2 is pure elementwise + pooling
    k_scatter2<<<(int)(((long long)N_EDGES * 4 + 255) / 256), 256>>>();
    k_node2_pool<<<(N_NODES * 16 + 255) / 256, 256>>>(batch_raw, b2);
    k_final<<<16, 256>>>(out);
}

// round 14
// speedup vs baseline: 1.1784x; 1.1784x over previous
#include <cuda_runtime.h>
#include <cuda_bf16.h>

#define N_NODES 100000
#define N_EDGES 3200000
#define N_GRAPHS 256
// DIMS: 38 -> 64 -> 32 -> 16

// ---------------- scratch (static device globals; no allocs) ----------------
__device__ float g_x40 [N_NODES * 40];
__device__ float g_agg0[N_NODES * 40];
__device__ float g_agg1[N_NODES * 32];
__device__ float g_agg2[N_NODES * 16];
__device__ float g_h1[N_NODES * 64];
__device__ float g_y1[N_NODES * 32];
__device__ float g_y2[N_NODES * 16];
__device__ float g_z2[N_NODES * 16];   // h2 @ Wroot2^T (node2 self term)
__device__ int   g_src[N_EDGES];
__device__ int   g_dst[N_EDGES];
__device__ float g_pool[N_GRAPHS * 16];
__device__ float g_cnt[N_GRAPHS];
__device__ int   g_ei_is64;
__device__ int   g_b_is64;

__device__ __forceinline__ void red_add_v4(float* addr, float4 v) {
    asm volatile("red.global.add.v4.f32 [%0], {%1,%2,%3,%4};"
                 :: "l"(addr), "f"(v.x), "f"(v.y), "f"(v.z), "f"(v.w)
                 : "memory");
}

// ---------------- dtype detection (int32 vs int64 buffers) ------------------
__global__ void k_detect(const int* __restrict__ ei_raw,
                         const int* __restrict__ b_raw) {
    int nz = 0;
    #pragma unroll
    for (int i = 0; i < 64; i++) nz |= ei_raw[2 * i + 1];
    g_ei_is64 = (nz == 0) ? 1 : 0;
    g_b_is64 = (b_raw[N_NODES - 1] == 0) ? 1 : 0;
}

// ---------------- fused prep: convert indices + zero + pack x ---------------
__global__ void k_prep(const float* __restrict__ x,
                       const int* __restrict__ ei_raw) {
    long long i = (long long)blockIdx.x * blockDim.x + threadIdx.x;
    long long stride = (long long)gridDim.x * blockDim.x;
    int is64 = g_ei_is64;
    for (long long e = i; e < N_EDGES; e += stride) {
        if (is64) {
            g_src[e] = ei_raw[2 * e];
            g_dst[e] = ei_raw[2 * ((long long)N_EDGES + e)];
        } else {
            g_src[e] = ei_raw[e];
            g_dst[e] = ei_raw[N_EDGES + e];
        }
    }
    for (long long k = i; k < (long long)N_NODES * 40; k += stride) {
        g_agg0[k] = 0.f;
        int j = (int)(k % 40);
        g_x40[k] = (j < 38) ? x[(k / 40) * 38 + j] : 0.f;
    }
    for (long long k = i; k < (long long)N_NODES * 32; k += stride) g_agg1[k] = 0.f;
    for (long long k = i; k < (long long)N_NODES * 16; k += stride) g_agg2[k] = 0.f;
    for (long long k = i; k < N_GRAPHS * 16; k += stride) g_pool[k] = 0.f;
    for (long long k = i; k < N_GRAPHS; k += stride) g_cnt[k] = 0.f;
}

// ---------------- scatters (proven at REDG/L2-byte floor) -------------------
__global__ void k_scatter0() {
    long long idx = (long long)blockIdx.x * blockDim.x + threadIdx.x;
    if (idx >= (long long)N_EDGES * 10) return;
    int e = (int)(idx / 10);
    int c = (int)(idx - (long long)e * 10);
    int s = g_src[e];
    int d = g_dst[e];
    float4 v = *(const float4*)&g_x40[s * 40 + c * 4];
    red_add_v4(&g_agg0[d * 40 + c * 4], v);
}

__global__ void k_scatter1() {
    long long idx = (long long)blockIdx.x * blockDim.x + threadIdx.x;
    if (idx >= (long long)N_EDGES * 8) return;
    int e = (int)(idx >> 3);
    int c = (int)(idx & 7);
    int s = g_src[e];
    int d = g_dst[e];
    float4 v = *(const float4*)&g_y1[s * 32 + c * 4];
    red_add_v4(&g_agg1[d * 32 + c * 4], v);
}

__global__ void k_scatter2() {
    long long idx = (long long)blockIdx.x * blockDim.x + threadIdx.x;
    if (idx >= (long long)N_EDGES * 4) return;
    int e = (int)(idx >> 2);
    int c = (int)(idx & 3);
    int s = g_src[e];
    int d = g_dst[e];
    float4 v = *(const float4*)&g_y2[s * 16 + c * 4];
    red_add_v4(&g_agg2[d * 16 + c * 4], v);
}

// ---------------- node kernel 0: 16 nodes/iter, ILP=4, 2 blocks/SM ----------
// (verbatim from the 501.8us baseline)
__global__ void __launch_bounds__(256, 2)
k_node0(const float* __restrict__ Wr0,  // [64,38]
        const float* __restrict__ b0,   // [64]
        const float* __restrict__ Wt0,  // [64,38]
        const float* __restrict__ Wr1)  // [32,64]
{
    int t = threadIdx.x;
    int o = t & 63, sl = t >> 6;
    float wr[40], wt[40];
    #pragma unroll
    for (int j = 0; j < 40; j++) {
        wr[j] = (j < 38) ? Wr0[o * 38 + j] : 0.f;
        wt[j] = (j < 38) ? Wt0[o * 38 + j] : 0.f;
    }
    float bias = b0[o];
    int oo = o & 31, jb = (o < 32) ? 0 : 32;

    __shared__ float  sW1[32 * 65];          // Wr1 [32x64] row stride 65
    __shared__ float4 sa4[16][10], sx4[16][10];
    __shared__ float  sh[16][64];
    __shared__ float  sp[16][64];
    for (int i = t; i < 32 * 64; i += 256) sW1[(i >> 6) * 65 + (i & 63)] = Wr1[i];
    __syncthreads();

    for (int nbase = blockIdx.x * 16; nbase < N_NODES; nbase += gridDim.x * 16) {
        for (int i = t; i < 320; i += 256) {
            int n2 = i / 20, r = i % 20;
            int nn = nbase + n2;
            if (nn < N_NODES) {
                if (r < 10) sa4[n2][r] = *(const float4*)&g_agg0[nn * 40 + r * 4];
                else        sx4[n2][r - 10] = *(const float4*)&g_x40[nn * 40 + (r - 10) * 4];
            }
        }
        __syncthreads();
        float h0 = bias, h1v = bias, h2v = bias, h3 = bias;
        #pragma unroll
        for (int c = 0; c < 10; c++) {
            float w0 = wr[4*c+0], w1_ = wr[4*c+1], w2_ = wr[4*c+2], w3 = wr[4*c+3];
            float u0 = wt[4*c+0], u1 = wt[4*c+1], u2 = wt[4*c+2], u3 = wt[4*c+3];
            float4 a, xv;
            a = sa4[sl][c];      xv = sx4[sl][c];
            h0 += w0*a.x + w1_*a.y + w2_*a.z + w3*a.w + u0*xv.x + u1*xv.y + u2*xv.z + u3*xv.w;
            a = sa4[sl+4][c];    xv = sx4[sl+4][c];
            h1v += w0*a.x + w1_*a.y + w2_*a.z + w3*a.w + u0*xv.x + u1*xv.y + u2*xv.z + u3*xv.w;
            a = sa4[sl+8][c];    xv = sx4[sl+8][c];
            h2v += w0*a.x + w1_*a.y + w2_*a.z + w3*a.w + u0*xv.x + u1*xv.y + u2*xv.z + u3*xv.w;
            a = sa4[sl+12][c];   xv = sx4[sl+12][c];
            h3 += w0*a.x + w1_*a.y + w2_*a.z + w3*a.w + u0*xv.x + u1*xv.y + u2*xv.z + u3*xv.w;
        }
        h0 = tanhf(h0); h1v = tanhf(h1v); h2v = tanhf(h2v); h3 = tanhf(h3);
        float hq[4] = {h0, h1v, h2v, h3};
        #pragma unroll
        for (int q = 0; q < 4; q++) {
            int nl = sl + 4 * q, node = nbase + nl;
            if (node < N_NODES) g_h1[node * 64 + o] = hq[q];
            sh[nl][o] = hq[q];
        }
        __syncthreads();
        #pragma unroll
        for (int q = 0; q < 4; q++) {
            int nl = sl + 4 * q;
            float p = 0.f;
            #pragma unroll
            for (int c = 0; c < 8; c++) {
                float4 hv = *(const float4*)&sh[nl][jb + c * 4];
                const float* wrow = &sW1[oo * 65 + jb + c * 4];
                p += wrow[0]*hv.x + wrow[1]*hv.y + wrow[2]*hv.z + wrow[3]*hv.w;
            }
            sp[nl][o] = p;
        }
        __syncthreads();
        if (o < 32) {
            #pragma unroll
            for (int q = 0; q < 4; q++) {
                int nl = sl + 4 * q, node = nbase + nl;
                if (node < N_NODES) g_y1[node * 32 + o] = sp[nl][o] + sp[nl][o + 32];
            }
        }
        __syncthreads();
    }
}

// ---------------- node kernel 1: h2 -> y2 AND z2 (no g_h2 round-trip) -------
// thread: o = t&31 (warp per node-slot), sl = t>>5 (8 slots); nl = sl + 8q.
__global__ void __launch_bounds__(256, 2)
k_node1(const float* __restrict__ b1,   // [32]
        const float* __restrict__ Wt1,  // [32,64]
        const float* __restrict__ Wr2,  // [16,32]
        const float* __restrict__ Wt2)  // [16,32]
{
    int t = threadIdx.x;
    int o = t & 31, sl = t >> 5;
    float wt1[64];
    #pragma unroll
    for (int j = 0; j < 64; j++) wt1[j] = Wt1[o * 64 + j];
    float bias = b1[o];
    int oo = o & 15, jb = (o < 16) ? 0 : 16;

    __shared__ float sW2y[16 * 33];          // Wrel2 [16x32] row stride 33
    __shared__ float sW2z[16 * 33];          // Wroot2 [16x32] row stride 33
    __shared__ float sh1[32][64];
    __shared__ float sh2[32][32];
    for (int i = t; i < 16 * 32; i += 256) {
        sW2y[(i >> 5) * 33 + (i & 31)] = Wr2[i];
        sW2z[(i >> 5) * 33 + (i & 31)] = Wt2[i];
    }
    __syncthreads();

    for (int nbase = blockIdx.x * 32; nbase < N_NODES; nbase += gridDim.x * 32) {
        for (int i = t; i < 512; i += 256) {
            int n2 = i >> 4, r = i & 15;
            int nn = nbase + n2;
            if (nn < N_NODES)
                *(float4*)&sh1[n2][r * 4] = *(const float4*)&g_h1[nn * 64 + r * 4];
        }
        __syncthreads();
        float hq[4];
        #pragma unroll
        for (int q = 0; q < 4; q++) {
            int nl = sl + 8 * q, node = nbase + nl;
            float h = bias;
            if (node < N_NODES) h += g_agg1[node * 32 + o];
            #pragma unroll
            for (int c = 0; c < 16; c++) {
                float4 hv = *(const float4*)&sh1[nl][c * 4];
                h += wt1[4*c+0]*hv.x + wt1[4*c+1]*hv.y + wt1[4*c+2]*hv.z + wt1[4*c+3]*hv.w;
            }
            hq[q] = tanhf(h);
        }
        #pragma unroll
        for (int q = 0; q < 4; q++) sh2[sl + 8 * q][o] = hq[q];
        __syncwarp();
        #pragma unroll
        for (int q = 0; q < 4; q++) {
            int nl = sl + 8 * q, node = nbase + nl;
            float py = 0.f, pz = 0.f;
            #pragma unroll
            for (int c = 0; c < 4; c++) {
                float4 hv = *(const float4*)&sh2[nl][jb + c * 4];
                const float* wy = &sW2y[oo * 33 + jb + c * 4];
                const float* wz = &sW2z[oo * 33 + jb + c * 4];
                py += wy[0]*hv.x + wy[1]*hv.y + wy[2]*hv.z + wy[3]*hv.w;
                pz += wz[0]*hv.x + wz[1]*hv.y + wz[2]*hv.z + wz[3]*hv.w;
            }
            float oy = __shfl_down_sync(0xffffffffu, py, 16);
            float oz = __shfl_down_sync(0xffffffffu, pz, 16);
            if (node < N_NODES && o < 16) {
                g_y2[node * 16 + o] = py + oy;
                g_z2[node * 16 + o] = pz + oz;
            }
        }
        __syncthreads();
    }
}

// ---------------- node kernel 2 + pooling: pure elementwise -----------------
__global__ void k_node2_pool(const int* __restrict__ batch_raw,
                             const float* __restrict__ b2)   // [16]
{
    int idx = blockIdx.x * blockDim.x + threadIdx.x;
    if (idx >= N_NODES * 16) return;
    int node = idx >> 4, o = idx & 15;
    float acc = g_agg2[idx] + g_z2[idx] + __ldg(&b2[o]);
    int g = g_b_is64 ? batch_raw[2 * node] : batch_raw[node];
    atomicAdd(&g_pool[g * 16 + o], acc);
    if (o == 0) atomicAdd(&g_cnt[g], 1.0f);
}

// ---------------- final: out = tanh(pool / max(cnt,1)) ----------------------
__global__ void k_final(float* __restrict__ out) {
    int t = blockIdx.x * blockDim.x + threadIdx.x;
    if (t < N_GRAPHS * 16) {
        int g = t >> 4;
        out[t] = tanhf(g_pool[t] / fmaxf(g_cnt[g], 1.0f));
    }
}

extern "C" void kernel_launch(void* const* d_in, const int* in_sizes, int n_in,
                              void* d_out, int out_size) {
    const float* x         = (const float*)d_in[0];
    const int*   ei_raw    = (const int*)d_in[1];
    const int*   batch_raw = (const int*)d_in[2];
    const float* Wr0 = (const float*)d_in[3];
    const float* b0  = (const float*)d_in[4];
    const float* Wt0 = (const float*)d_in[5];
    const float* Wr1 = (const float*)d_in[6];
    const float* b1  = (const float*)d_in[7];
    const float* Wt1 = (const float*)d_in[8];
    const float* Wr2 = (const float*)d_in[9];
    const float* b2  = (const float*)d_in[10];
    const float* Wt2 = (const float*)d_in[11];
    float* out = (float*)d_out;

    k_detect<<<1, 1>>>(ei_raw, batch_raw);
    k_prep<<<2048, 256>>>(x, ei_raw);
    k_scatter0<<<(int)(((long long)N_EDGES * 10 + 255) / 256), 256>>>();
    k_node0<<<592, 256>>>(Wr0, b0, Wt0, Wr1);
    k_scatter1<<<(int)(((long long)N_EDGES * 8 + 255) / 256), 256>>>();
    k_node1<<<592, 256>>>(b1, Wt1, Wr2, Wt2);
    k_scatter2<<<(int)(((long long)N_EDGES * 4 + 255) / 256), 256>>>();
    k_node2_pool<<<(N_NODES * 16 + 255) / 256, 256>>>(batch_raw, b2);
    k_final<<<16, 256>>>(out);
}

// round 15
// speedup vs baseline: 1.3944x; 1.1833x over previous
#include <cuda_runtime.h>
#include <cuda_bf16.h>

#define N_NODES 100000
#define N_EDGES 3200000
#define N_GRAPHS 256
// DIMS: 38 -> 64 -> 32 -> 16

// ---------------- scratch (static device globals; no allocs) ----------------
__device__ float g_x40 [N_NODES * 40];
__device__ float g_agg0[N_NODES * 40];
__device__ float g_agg1[N_NODES * 32];
__device__ float g_agg2[N_NODES * 16];
__device__ float g_h1[N_NODES * 64];
__device__ float g_y1[N_NODES * 32];
__device__ float g_y2[N_NODES * 16];
__device__ float g_z2[N_NODES * 16];
__device__ int   g_src[N_EDGES];
__device__ int   g_dst[N_EDGES];
__device__ int   g_ssrc[N_EDGES];       // src sorted by dst (CSR payload)
__device__ int   g_rowptr[N_NODES + 1];
__device__ int   g_cursor[N_NODES];
__device__ int   g_blocksum[512];
__device__ float g_pool[N_GRAPHS * 16];
__device__ float g_cnt[N_GRAPHS];
__device__ int   g_ei_is64;
__device__ int   g_b_is64;

// ---------------- dtype detection (int32 vs int64 buffers) ------------------
__global__ void k_detect(const int* __restrict__ ei_raw,
                         const int* __restrict__ b_raw) {
    int nz = 0;
    #pragma unroll
    for (int i = 0; i < 64; i++) nz |= ei_raw[2 * i + 1];
    g_ei_is64 = (nz == 0) ? 1 : 0;
    g_b_is64 = (b_raw[N_NODES - 1] == 0) ? 1 : 0;
}

// ---------------- prep: convert indices, pack x, zero small bufs ------------
__global__ void k_prep(const float* __restrict__ x,
                       const int* __restrict__ ei_raw) {
    long long i = (long long)blockIdx.x * blockDim.x + threadIdx.x;
    long long stride = (long long)gridDim.x * blockDim.x;
    int is64 = g_ei_is64;
    for (long long e = i; e < N_EDGES; e += stride) {
        if (is64) {
            g_src[e] = ei_raw[2 * e];
            g_dst[e] = ei_raw[2 * ((long long)N_EDGES + e)];
        } else {
            g_src[e] = ei_raw[e];
            g_dst[e] = ei_raw[N_EDGES + e];
        }
    }
    for (long long k = i; k < (long long)N_NODES * 40; k += stride) {
        int j = (int)(k % 40);
        g_x40[k] = (j < 38) ? x[(k / 40) * 38 + j] : 0.f;
    }
    for (long long k = i; k < N_NODES; k += stride) g_cursor[k] = 0;
    for (long long k = i; k < N_GRAPHS * 16; k += stride) g_pool[k] = 0.f;
    for (long long k = i; k < N_GRAPHS; k += stride) g_cnt[k] = 0.f;
}

// ---------------- CSR build: histogram -> scan -> place (proven R9) ---------
__global__ void k_hist() {
    int i = blockIdx.x * blockDim.x + threadIdx.x;
    int stride = gridDim.x * blockDim.x;
    for (int e = i; e < N_EDGES; e += stride)
        atomicAdd(&g_cursor[g_dst[e]], 1);
}

__global__ void k_scan1() {
    __shared__ int sh[256];
    int i = blockIdx.x * 256 + threadIdx.x;
    int v = (i < N_NODES) ? g_cursor[i] : 0;
    sh[threadIdx.x] = v;
    __syncthreads();
    for (int off = 1; off < 256; off <<= 1) {
        int t = (threadIdx.x >= off) ? sh[threadIdx.x - off] : 0;
        __syncthreads();
        sh[threadIdx.x] += t;
        __syncthreads();
    }
    if (i < N_NODES) g_rowptr[i] = sh[threadIdx.x] - v;
    if (threadIdx.x == 255) g_blocksum[blockIdx.x] = sh[255];
}

__global__ void k_scan2() {
    __shared__ int sh[512];
    int v = (threadIdx.x < 391) ? g_blocksum[threadIdx.x] : 0;
    sh[threadIdx.x] = v;
    __syncthreads();
    for (int off = 1; off < 512; off <<= 1) {
        int t = (threadIdx.x >= off) ? sh[threadIdx.x - off] : 0;
        __syncthreads();
        sh[threadIdx.x] += t;
        __syncthreads();
    }
    if (threadIdx.x < 391) g_blocksum[threadIdx.x] = sh[threadIdx.x] - v;
}

__global__ void k_scan3() {
    int i = blockIdx.x * 256 + threadIdx.x;
    if (i < N_NODES) {
        int r = g_rowptr[i] + g_blocksum[blockIdx.x];
        g_rowptr[i] = r;
        g_cursor[i] = r;
    }
    if (i == 0) g_rowptr[N_NODES] = N_EDGES;
}

__global__ void k_place() {
    int i = blockIdx.x * blockDim.x + threadIdx.x;
    int stride = gridDim.x * blockDim.x;
    for (int e = i; e < N_EDGES; e += stride) {
        int d = g_dst[e];
        int p = atomicAdd(&g_cursor[d], 1);
        g_ssrc[p] = g_src[e];
    }
}

// ---------------- CSR gather-sum: warp-per-node, lane = feature -------------
// agg0: 40 features (lane + lane+32 for lane<8). Edge list read once/warp.
__global__ void k_agg0() {
    int w = (blockIdx.x * blockDim.x + threadIdx.x) >> 5;
    int lane = threadIdx.x & 31;
    if (w >= N_NODES) return;
    int beg = g_rowptr[w], end = g_rowptr[w + 1];
    float a = 0.f, b = 0.f;
    int k = beg;
    for (; k + 4 <= end; k += 4) {
        int s0 = g_ssrc[k], s1 = g_ssrc[k+1], s2 = g_ssrc[k+2], s3 = g_ssrc[k+3];
        float v0 = g_x40[s0 * 40 + lane];
        float v1 = g_x40[s1 * 40 + lane];
        float v2 = g_x40[s2 * 40 + lane];
        float v3 = g_x40[s3 * 40 + lane];
        a += (v0 + v1) + (v2 + v3);
        if (lane < 8) {
            float u0 = g_x40[s0 * 40 + 32 + lane];
            float u1 = g_x40[s1 * 40 + 32 + lane];
            float u2 = g_x40[s2 * 40 + 32 + lane];
            float u3 = g_x40[s3 * 40 + 32 + lane];
            b += (u0 + u1) + (u2 + u3);
        }
    }
    for (; k < end; k++) {
        int s = g_ssrc[k];
        a += g_x40[s * 40 + lane];
        if (lane < 8) b += g_x40[s * 40 + 32 + lane];
    }
    g_agg0[w * 40 + lane] = a;
    if (lane < 8) g_agg0[w * 40 + 32 + lane] = b;
}

// agg1: 32 features, lane = feature.
__global__ void k_agg1() {
    int w = (blockIdx.x * blockDim.x + threadIdx.x) >> 5;
    int lane = threadIdx.x & 31;
    if (w >= N_NODES) return;
    int beg = g_rowptr[w], end = g_rowptr[w + 1];
    float a = 0.f;
    int k = beg;
    for (; k + 4 <= end; k += 4) {
        int s0 = g_ssrc[k], s1 = g_ssrc[k+1], s2 = g_ssrc[k+2], s3 = g_ssrc[k+3];
        float v0 = g_y1[s0 * 32 + lane];
        float v1 = g_y1[s1 * 32 + lane];
        float v2 = g_y1[s2 * 32 + lane];
        float v3 = g_y1[s3 * 32 + lane];
        a += (v0 + v1) + (v2 + v3);
    }
    for (; k < end; k++)
        a += g_y1[g_ssrc[k] * 32 + lane];
    g_agg1[w * 32 + lane] = a;
}

// agg2: 16 features, half-warp per node.
__global__ void k_agg2() {
    int tid = blockIdx.x * blockDim.x + threadIdx.x;
    int n = tid >> 4;
    int f = tid & 15;
    if (n >= N_NODES) return;
    int beg = g_rowptr[n], end = g_rowptr[n + 1];
    float a = 0.f;
    int k = beg;
    for (; k + 4 <= end; k += 4) {
        int s0 = g_ssrc[k], s1 = g_ssrc[k+1], s2 = g_ssrc[k+2], s3 = g_ssrc[k+3];
        float v0 = g_y2[s0 * 16 + f];
        float v1 = g_y2[s1 * 16 + f];
        float v2 = g_y2[s2 * 16 + f];
        float v3 = g_y2[s3 * 16 + f];
        a += (v0 + v1) + (v2 + v3);
    }
    for (; k < end; k++)
        a += g_y2[g_ssrc[k] * 16 + f];
    g_agg2[n * 16 + f] = a;
}

// ---------------- node kernel 0: 16 nodes/iter, ILP=4, 2 blocks/SM ----------
__global__ void __launch_bounds__(256, 2)
k_node0(const float* __restrict__ Wr0,  // [64,38]
        const float* __restrict__ b0,   // [64]
        const float* __restrict__ Wt0,  // [64,38]
        const float* __restrict__ Wr1)  // [32,64]
{
    int t = threadIdx.x;
    int o = t & 63, sl = t >> 6;
    float wr[40], wt[40];
    #pragma unroll
    for (int j = 0; j < 40; j++) {
        wr[j] = (j < 38) ? Wr0[o * 38 + j] : 0.f;
        wt[j] = (j < 38) ? Wt0[o * 38 + j] : 0.f;
    }
    float bias = b0[o];
    int oo = o & 31, jb = (o < 32) ? 0 : 32;

    __shared__ float  sW1[32 * 65];
    __shared__ float4 sa4[16][10], sx4[16][10];
    __shared__ float  sh[16][64];
    __shared__ float  sp[16][64];
    for (int i = t; i < 32 * 64; i += 256) sW1[(i >> 6) * 65 + (i & 63)] = Wr1[i];
    __syncthreads();

    for (int nbase = blockIdx.x * 16; nbase < N_NODES; nbase += gridDim.x * 16) {
        for (int i = t; i < 320; i += 256) {
            int n2 = i / 20, r = i % 20;
            int nn = nbase + n2;
            if (nn < N_NODES) {
                if (r < 10) sa4[n2][r] = *(const float4*)&g_agg0[nn * 40 + r * 4];
                else        sx4[n2][r - 10] = *(const float4*)&g_x40[nn * 40 + (r - 10) * 4];
            }
        }
        __syncthreads();
        float h0 = bias, h1v = bias, h2v = bias, h3 = bias;
        #pragma unroll
        for (int c = 0; c < 10; c++) {
            float w0 = wr[4*c+0], w1_ = wr[4*c+1], w2_ = wr[4*c+2], w3 = wr[4*c+3];
            float u0 = wt[4*c+0], u1 = wt[4*c+1], u2 = wt[4*c+2], u3 = wt[4*c+3];
            float4 a, xv;
            a = sa4[sl][c];      xv = sx4[sl][c];
            h0 += w0*a.x + w1_*a.y + w2_*a.z + w3*a.w + u0*xv.x + u1*xv.y + u2*xv.z + u3*xv.w;
            a = sa4[sl+4][c];    xv = sx4[sl+4][c];
            h1v += w0*a.x + w1_*a.y + w2_*a.z + w3*a.w + u0*xv.x + u1*xv.y + u2*xv.z + u3*xv.w;
            a = sa4[sl+8][c];    xv = sx4[sl+8][c];
            h2v += w0*a.x + w1_*a.y + w2_*a.z + w3*a.w + u0*xv.x + u1*xv.y + u2*xv.z + u3*xv.w;
            a = sa4[sl+12][c];   xv = sx4[sl+12][c];
            h3 += w0*a.x + w1_*a.y + w2_*a.z + w3*a.w + u0*xv.x + u1*xv.y + u2*xv.z + u3*xv.w;
        }
        h0 = tanhf(h0); h1v = tanhf(h1v); h2v = tanhf(h2v); h3 = tanhf(h3);
        float hq[4] = {h0, h1v, h2v, h3};
        #pragma unroll
        for (int q = 0; q < 4; q++) {
            int nl = sl + 4 * q, node = nbase + nl;
            if (node < N_NODES) g_h1[node * 64 + o] = hq[q];
            sh[nl][o] = hq[q];
        }
        __syncthreads();
        #pragma unroll
        for (int q = 0; q < 4; q++) {
            int nl = sl + 4 * q;
            float p = 0.f;
            #pragma unroll
            for (int c = 0; c < 8; c++) {
                float4 hv = *(const float4*)&sh[nl][jb + c * 4];
                const float* wrow = &sW1[oo * 65 + jb + c * 4];
                p += wrow[0]*hv.x + wrow[1]*hv.y + wrow[2]*hv.z + wrow[3]*hv.w;
            }
            sp[nl][o] = p;
        }
        __syncthreads();
        if (o < 32) {
            #pragma unroll
            for (int q = 0; q < 4; q++) {
                int nl = sl + 4 * q, node = nbase + nl;
                if (node < N_NODES) g_y1[node * 32 + o] = sp[nl][o] + sp[nl][o + 32];
            }
        }
        __syncthreads();
    }
}

// ---------------- node kernel 1: h2 -> y2 AND z2 (no g_h2 round-trip) -------
__global__ void __launch_bounds__(256, 2)
k_node1(const float* __restrict__ b1,   // [32]
        const float* __restrict__ Wt1,  // [32,64]
        const float* __restrict__ Wr2,  // [16,32]
        const float* __restrict__ Wt2)  // [16,32]
{
    int t = threadIdx.x;
    int o = t & 31, sl = t >> 5;
    float wt1[64];
    #pragma unroll
    for (int j = 0; j < 64; j++) wt1[j] = Wt1[o * 64 + j];
    float bias = b1[o];
    int oo = o & 15, jb = (o < 16) ? 0 : 16;

    __shared__ float sW2y[16 * 33];
    __shared__ float sW2z[16 * 33];
    __shared__ float sh1[32][64];
    __shared__ float sh2[32][32];
    for (int i = t; i < 16 * 32; i += 256) {
        sW2y[(i >> 5) * 33 + (i & 31)] = Wr2[i];
        sW2z[(i >> 5) * 33 + (i & 31)] = Wt2[i];
    }
    __syncthreads();

    for (int nbase = blockIdx.x * 32; nbase < N_NODES; nbase += gridDim.x * 32) {
        for (int i = t; i < 512; i += 256) {
            int n2 = i >> 4, r = i & 15;
            int nn = nbase + n2;
            if (nn < N_NODES)
                *(float4*)&sh1[n2][r * 4] = *(const float4*)&g_h1[nn * 64 + r * 4];
        }
        __syncthreads();
        float hq[4];
        #pragma unroll
        for (int q = 0; q < 4; q++) {
            int nl = sl + 8 * q, node = nbase + nl;
            float h = bias;
            if (node < N_NODES) h += g_agg1[node * 32 + o];
            #pragma unroll
            for (int c = 0; c < 16; c++) {
                float4 hv = *(const float4*)&sh1[nl][c * 4];
                h += wt1[4*c+0]*hv.x + wt1[4*c+1]*hv.y + wt1[4*c+2]*hv.z + wt1[4*c+3]*hv.w;
            }
            hq[q] = tanhf(h);
        }
        #pragma unroll
        for (int q = 0; q < 4; q++) sh2[sl + 8 * q][o] = hq[q];
        __syncwarp();
        #pragma unroll
        for (int q = 0; q < 4; q++) {
            int nl = sl + 8 * q, node = nbase + nl;
            float py = 0.f, pz = 0.f;
            #pragma unroll
            for (int c = 0; c < 4; c++) {
                float4 hv = *(const float4*)&sh2[nl][jb + c * 4];
                const float* wy = &sW2y[oo * 33 + jb + c * 4];
                const float* wz = &sW2z[oo * 33 + jb + c * 4];
                py += wy[0]*hv.x + wy[1]*hv.y + wy[2]*hv.z + wy[3]*hv.w;
                pz += wz[0]*hv.x + wz[1]*hv.y + wz[2]*hv.z + wz[3]*hv.w;
            }
            float oy = __shfl_down_sync(0xffffffffu, py, 16);
            float oz = __shfl_down_sync(0xffffffffu, pz, 16);
            if (node < N_NODES && o < 16) {
                g_y2[node * 16 + o] = py + oy;
                g_z2[node * 16 + o] = pz + oz;
            }
        }
        __syncthreads();
    }
}

// ---------------- node kernel 2 + pooling: pure elementwise -----------------
__global__ void k_node2_pool(const int* __restrict__ batch_raw,
                             const float* __restrict__ b2)   // [16]
{
    int idx = blockIdx.x * blockDim.x + threadIdx.x;
    if (idx >= N_NODES * 16) return;
    int node = idx >> 4, o = idx & 15;
    float acc = g_agg2[idx] + g_z2[idx] + __ldg(&b2[o]);
    int g = g_b_is64 ? batch_raw[2 * node] : batch_raw[node];
    atomicAdd(&g_pool[g * 16 + o], acc);
    if (o == 0) atomicAdd(&g_cnt[g], 1.0f);
}

// ---------------- final: out = tanh(pool / max(cnt,1)) ----------------------
__global__ void k_final(float* __restrict__ out) {
    int t = blockIdx.x * blockDim.x + threadIdx.x;
    if (t < N_GRAPHS * 16) {
        int g = t >> 4;
        out[t] = tanhf(g_pool[t] / fmaxf(g_cnt[g], 1.0f));
    }
}

extern "C" void kernel_launch(void* const* d_in, const int* in_sizes, int n_in,
                              void* d_out, int out_size) {
    const float* x         = (const float*)d_in[0];
    const int*   ei_raw    = (const int*)d_in[1];
    const int*   batch_raw = (const int*)d_in[2];
    const float* Wr0 = (const float*)d_in[3];
    const float* b0  = (const float*)d_in[4];
    const float* Wt0 = (const float*)d_in[5];
    const float* Wr1 = (const float*)d_in[6];
    const float* b1  = (const float*)d_in[7];
    const float* Wt1 = (const float*)d_in[8];
    const float* Wr2 = (const float*)d_in[9];
    const float* b2  = (const float*)d_in[10];
    const float* Wt2 = (const float*)d_in[11];
    float* out = (float*)d_out;

    k_detect<<<1, 1>>>(ei_raw, batch_raw);
    k_prep<<<2048, 256>>>(x, ei_raw);
    // CSR build (once, reused by all 3 layers)
    k_hist<<<2048, 256>>>();
    k_scan1<<<391, 256>>>();
    k_scan2<<<1, 512>>>();
    k_scan3<<<391, 256>>>();
    k_place<<<2048, 256>>>();
    // layer 0
    k_agg0<<<(N_NODES * 32 + 255) / 256, 256>>>();
    k_node0<<<592, 256>>>(Wr0, b0, Wt0, Wr1);
    // layer 1
    k_agg1<<<(N_NODES * 32 + 255) / 256, 256>>>();
    k_node1<<<592, 256>>>(b1, Wt1, Wr2, Wt2);
    // layer 2
    k_agg2<<<(N_NODES * 16 + 255) / 256, 256>>>();
    k_node2_pool<<<(N_NODES * 16 + 255) / 256, 256>>>(batch_raw, b2);
    k_final<<<16, 256>>>(out);
}